// round 1
// baseline (speedup 1.0000x reference)
#include <cuda_runtime.h>
#include <cuda_bf16.h>

// Problem constants
#define BATCH 16
#define CIN   256
#define DMODEL 256
#define HEADS 8
#define NPH   32      // channels per head
#define HDIM  56
#define LTOT  3136    // 56*56
#define KWIN  9

// ---------------- device scratch ----------------
__device__ float g_wq[BATCH * HEADS * CIN];             // 128 KB
__device__ float g_s[BATCH * HEADS * LTOT];             // 1.6 MB
__device__ float g_v[BATCH * DMODEL * LTOT];            // 51.4 MB
__device__ float g_attn[BATCH * HEADS * KWIN * LTOT];   // 14.4 MB
__device__ float g_out[BATCH * DMODEL * LTOT];          // 51.4 MB

// ---------------- K1: wq[b,h,c] = sum_n q[b,h*32+n] * Wk[h*32+n, c] ----------------
__global__ void wq_kernel(const float* __restrict__ q, const float* __restrict__ Wk) {
    int bh = blockIdx.x;                 // 0..127
    int b = bh >> 3, h = bh & 7;
    __shared__ float qs[NPH];
    if (threadIdx.x < NPH) qs[threadIdx.x] = q[b * DMODEL + h * NPH + threadIdx.x];
    __syncthreads();
    int c = threadIdx.x;                 // 256 threads
    float acc = 0.f;
#pragma unroll
    for (int n = 0; n < NPH; n++)
        acc += qs[n] * Wk[(h * NPH + n) * CIN + c];
    g_wq[bh * CIN + c] = acc;
}

// ---------------- K2: batched SGEMM  C[b,m,l] = sum_c A[m,c] * X[b,c,l] ----------------
// M=256, K=256, L=3136 (=49*64). 64x64 tiles, 256 threads, 4x4 per thread.
__global__ void sgemm64(const float* __restrict__ A, const float* __restrict__ X,
                        float* __restrict__ C) {
    const int b  = blockIdx.z;
    const int m0 = blockIdx.y * 64;
    const int n0 = blockIdx.x * 64;
    const float* Xb = X + (size_t)b * DMODEL * LTOT;
    float* Cb       = C + (size_t)b * DMODEL * LTOT;

    __shared__ float As[16][64];   // [k][m]
    __shared__ float Bs[16][64];   // [k][n]

    const int tid = threadIdx.x;
    const int tx = tid & 15;       // 0..15
    const int ty = tid >> 4;       // 0..15

    float acc[4][4] = {};

    for (int k0 = 0; k0 < 256; k0 += 16) {
        // Load A tile (64 rows x 16 cols), transpose into As[k][m]
        {
            int r  = tid >> 2;             // 0..63
            int c4 = (tid & 3) << 2;       // 0,4,8,12
            float4 a = *reinterpret_cast<const float4*>(A + (m0 + r) * 256 + k0 + c4);
            As[c4 + 0][r] = a.x;
            As[c4 + 1][r] = a.y;
            As[c4 + 2][r] = a.z;
            As[c4 + 3][r] = a.w;
        }
        // Load B tile (16 rows x 64 cols)
        {
            int kr = tid >> 4;             // 0..15
            int c4 = (tid & 15) << 2;      // 0..60
            float4 v = *reinterpret_cast<const float4*>(Xb + (size_t)(k0 + kr) * LTOT + n0 + c4);
            *reinterpret_cast<float4*>(&Bs[kr][c4]) = v;
        }
        __syncthreads();
#pragma unroll
        for (int kk = 0; kk < 16; kk++) {
            float a[4], bv[4];
#pragma unroll
            for (int i = 0; i < 4; i++) a[i] = As[kk][ty * 4 + i];
#pragma unroll
            for (int j = 0; j < 4; j++) bv[j] = Bs[kk][tx * 4 + j];
#pragma unroll
            for (int i = 0; i < 4; i++)
#pragma unroll
                for (int j = 0; j < 4; j++)
                    acc[i][j] += a[i] * bv[j];
        }
        __syncthreads();
    }
#pragma unroll
    for (int i = 0; i < 4; i++) {
        int m = m0 + ty * 4 + i;
        float4 v = make_float4(acc[i][0], acc[i][1], acc[i][2], acc[i][3]);
        *reinterpret_cast<float4*>(Cb + (size_t)m * LTOT + n0 + tx * 4) = v;
    }
}

// ---------------- K3: s[b,h,l] = sum_c wq[b,h,c] * x[b,c,l]  (8 heads per x read) ----------------
__global__ void s_kernel(const float* __restrict__ x) {
    __shared__ float wq_s[HEADS * CIN];   // 8 KB
    const int b = blockIdx.y;
    for (int i = threadIdx.x; i < HEADS * CIN; i += 256)
        wq_s[i] = g_wq[b * HEADS * CIN + i];
    __syncthreads();
    int l = blockIdx.x * 256 + threadIdx.x;
    if (l >= LTOT) return;
    const float* xb = x + (size_t)b * CIN * LTOT;
    float acc[HEADS] = {};
    for (int c = 0; c < CIN; c++) {
        float xv = xb[(size_t)c * LTOT + l];
#pragma unroll
        for (int h = 0; h < HEADS; h++)
            acc[h] += wq_s[h * CIN + c] * xv;
    }
#pragma unroll
    for (int h = 0; h < HEADS; h++)
        g_s[(size_t)(b * HEADS + h) * LTOT + l] = acc[h];
}

// ---------------- K4: softmax over 9 taps + rel-pos bias + Wlin scale ----------------
// attn layout: [(bh*9 + k)*L + l]
__global__ void attn_kernel(const float* __restrict__ pos_emb, const float* __restrict__ Wlin) {
    int bh = blockIdx.y;
    int l  = blockIdx.x * 256 + threadIdx.x;
    if (l >= LTOT) return;
    float scale = Wlin[0] + Wlin[1] + Wlin[2] + Wlin[3];
    int y = l / HDIM, xx = l % HDIM;
    const float* sp = g_s + (size_t)bh * LTOT;
    float logit[KWIN];
#pragma unroll
    for (int kh = 0; kh < 3; kh++)
#pragma unroll
        for (int kw = 0; kw < 3; kw++) {
            int yy = y + kh - 1, xz = xx + kw - 1;
            float sv = (yy >= 0 && yy < HDIM && xz >= 0 && xz < HDIM)
                           ? sp[yy * HDIM + xz] : 0.f;   // unfold zero-padding
            logit[kh * 3 + kw] = sv + pos_emb[kh + kw];  // REL[kh*3+kw] = kh+kw
        }
    float m = logit[0];
#pragma unroll
    for (int k = 1; k < KWIN; k++) m = fmaxf(m, logit[k]);
    float e[KWIN], sum = 0.f;
#pragma unroll
    for (int k = 0; k < KWIN; k++) { e[k] = __expf(logit[k] - m); sum += e[k]; }
    float inv = scale / sum;
    float* ap = g_attn + (size_t)(bh * KWIN) * LTOT + l;
#pragma unroll
    for (int k = 0; k < KWIN; k++)
        ap[(size_t)k * LTOT] = e[k] * inv;
}

// ---------------- K5: out[b,d,l] = sum_k attn[b,h,k,l] * v[b,d, l+off_k] ----------------
__global__ void av_kernel() {
    int bd = blockIdx.y;                  // b*256 + d
    int b = bd >> 8, d = bd & 255;
    int h = d >> 5;
    int l = blockIdx.x * 256 + threadIdx.x;
    if (l >= LTOT) return;
    int y = l / HDIM, xx = l % HDIM;
    const float* ap = g_attn + (size_t)((b * HEADS + h) * KWIN) * LTOT + l;
    const float* vp = g_v + (size_t)bd * LTOT;
    float acc = 0.f;
#pragma unroll
    for (int kh = 0; kh < 3; kh++) {
        int yy = y + kh - 1;
        if (yy < 0 || yy >= HDIM) continue;
#pragma unroll
        for (int kw = 0; kw < 3; kw++) {
            int xz = xx + kw - 1;
            if (xz < 0 || xz >= HDIM) continue;
            acc += ap[(size_t)(kh * 3 + kw) * LTOT] * vp[yy * HDIM + xz];
        }
    }
    g_out[(size_t)bd * LTOT + l] = acc;
}

// ---------------- host launcher ----------------
extern "C" void kernel_launch(void* const* d_in, const int* in_sizes, int n_in,
                              void* d_out, int out_size) {
    const float* x       = (const float*)d_in[0];
    const float* q       = (const float*)d_in[1];
    const float* Wk      = (const float*)d_in[2];
    const float* Wv      = (const float*)d_in[3];
    const float* pos_emb = (const float*)d_in[4];
    const float* Wlin    = (const float*)d_in[5];
    const float* Wproj   = (const float*)d_in[6];
    float* out = (float*)d_out;

    void *pv = nullptr, *pout = nullptr;
    cudaGetSymbolAddress(&pv, g_v);
    cudaGetSymbolAddress(&pout, g_out);

    const int LBLKS = (LTOT + 255) / 256;   // 13

    wq_kernel<<<BATCH * HEADS, 256>>>(q, Wk);
    sgemm64<<<dim3(LTOT / 64, DMODEL / 64, BATCH), 256>>>(Wv, x, (float*)pv);
    s_kernel<<<dim3(LBLKS, BATCH), 256>>>(x);
    attn_kernel<<<dim3(LBLKS, BATCH * HEADS), 256>>>(pos_emb, Wlin);
    av_kernel<<<dim3(LBLKS, BATCH * DMODEL), 256>>>();
    sgemm64<<<dim3(LTOT / 64, DMODEL / 64, BATCH), 256>>>(Wproj, (const float*)pout, out);
}

// round 3
// speedup vs baseline: 1.7348x; 1.7348x over previous
#include <cuda_runtime.h>
#include <cuda_fp16.h>
#include <cstdint>

#define BATCH 16
#define CIN   256
#define DMODEL 256
#define HEADS 8
#define NPH   32
#define HDIM  56
#define LTOT  3136
#define KWIN  9

// ---------------- device scratch ----------------
__device__ float g_wq[BATCH * HEADS * CIN];
__device__ float g_s[BATCH * HEADS * LTOT];
__device__ float g_v[BATCH * DMODEL * LTOT];
__device__ float g_attn[BATCH * HEADS * KWIN * LTOT];
__device__ __align__(16) __half g_xhi[BATCH * CIN * LTOT];
__device__ __align__(16) __half g_xlo[BATCH * CIN * LTOT];
__device__ __align__(16) __half g_ohi[BATCH * DMODEL * LTOT];
__device__ __align__(16) __half g_olo[BATCH * DMODEL * LTOT];
__device__ __align__(16) __half g_wvhi[DMODEL * CIN];
__device__ __align__(16) __half g_wvlo[DMODEL * CIN];
__device__ __align__(16) __half g_wphi[DMODEL * DMODEL];
__device__ __align__(16) __half g_wplo[DMODEL * DMODEL];

// ---------------- PTX helpers ----------------
__device__ __forceinline__ uint32_t smem_u32(const void* p) {
    uint32_t a;
    asm("{ .reg .u64 t; cvta.to.shared.u64 t, %1; cvt.u32.u64 %0, t; }" : "=r"(a) : "l"(p));
    return a;
}
__device__ __forceinline__ void ldmA(uint32_t* r, uint32_t addr) {
    asm volatile("ldmatrix.sync.aligned.m8n8.x4.shared.b16 {%0,%1,%2,%3}, [%4];"
                 : "=r"(r[0]), "=r"(r[1]), "=r"(r[2]), "=r"(r[3]) : "r"(addr));
}
__device__ __forceinline__ void ldmBt(uint32_t* r, uint32_t addr) {
    asm volatile("ldmatrix.sync.aligned.m8n8.x2.trans.shared.b16 {%0,%1}, [%2];"
                 : "=r"(r[0]), "=r"(r[1]) : "r"(addr));
}
__device__ __forceinline__ void hmma(float* d, const uint32_t* a, const uint32_t* b) {
    asm volatile("mma.sync.aligned.m16n8k16.row.col.f32.f16.f16.f32 "
                 "{%0,%1,%2,%3}, {%4,%5,%6,%7}, {%8,%9}, {%0,%1,%2,%3};"
                 : "+f"(d[0]), "+f"(d[1]), "+f"(d[2]), "+f"(d[3])
                 : "r"(a[0]), "r"(a[1]), "r"(a[2]), "r"(a[3]), "r"(b[0]), "r"(b[1]));
}
__device__ __forceinline__ void cp16(uint32_t dst, const void* src) {
    asm volatile("cp.async.cg.shared.global [%0], [%1], 16;" :: "r"(dst), "l"(src));
}
#define CP_COMMIT() asm volatile("cp.async.commit_group;" ::: "memory")
#define CP_WAIT(n)  asm volatile("cp.async.wait_group %0;" :: "n"(n) : "memory")

__device__ __forceinline__ uint32_t sw128(uint32_t b) { return b ^ ((b >> 3) & 0x70); }

// ---------------- K0: hi/lo fp16 split ----------------
__global__ void split_kernel(const float* __restrict__ src, __half* __restrict__ hi,
                             __half* __restrict__ lo, int n4) {
    int i = blockIdx.x * 256 + threadIdx.x;
    if (i >= n4) return;
    float4 v = reinterpret_cast<const float4*>(src)[i];
    float vv[4] = {v.x, v.y, v.z, v.w};
    __half h[4], l[4];
#pragma unroll
    for (int j = 0; j < 4; j++) {
        h[j] = __float2half(vv[j]);
        l[j] = __float2half(vv[j] - __half2float(h[j]));
    }
    __half2* H = reinterpret_cast<__half2*>(hi);
    __half2* L = reinterpret_cast<__half2*>(lo);
    H[2 * i]     = __half2(h[0], h[1]);
    H[2 * i + 1] = __half2(h[2], h[3]);
    L[2 * i]     = __half2(l[0], l[1]);
    L[2 * i + 1] = __half2(l[2], l[3]);
}

// ---------------- K1: wq[b,h,c] = sum_n q[b,h*32+n] * Wk[h*32+n, c] ----------------
__global__ void wq_kernel(const float* __restrict__ q, const float* __restrict__ Wk) {
    int bh = blockIdx.x;
    int b = bh >> 3, h = bh & 7;
    __shared__ float qs[NPH];
    if (threadIdx.x < NPH) qs[threadIdx.x] = q[b * DMODEL + h * NPH + threadIdx.x];
    __syncthreads();
    int c = threadIdx.x;
    float acc = 0.f;
#pragma unroll
    for (int n = 0; n < NPH; n++) acc += qs[n] * Wk[(h * NPH + n) * CIN + c];
    g_wq[bh * CIN + c] = acc;
}

// ---------------- K2: HMMA split-fp16 GEMM  C[b,m,l] = sum_c A[m,c]*X[b,c,l] ----------------
// CTA tile M=128, N=64. 8 warps of 32x32. K-chunks of 64, virtual K = 3*256 (hh, hl, lh).
__global__ void __launch_bounds__(256) hgemm(
    const __half* __restrict__ Ahi, const __half* __restrict__ Alo,
    const __half* __restrict__ Bhi, const __half* __restrict__ Blo,
    float* __restrict__ C) {
    __shared__ __align__(1024) __half sA[2][128 * 64];   // 32 KB
    __shared__ __align__(1024) __half sX[2][64 * 64];    // 16 KB

    const int tid = threadIdx.x;
    const int wid = tid >> 5, lane = tid & 31;
    const int l0 = blockIdx.x * 64;
    const int m0 = blockIdx.y * 128;
    const int b  = blockIdx.z;

    const int m_base = (wid >> 1) * 32;
    const int n_base = (wid & 1) * 32;

    const __half* Bhi_b = Bhi + (size_t)b * CIN * LTOT;
    const __half* Blo_b = Blo + (size_t)b * CIN * LTOT;

    const uint32_t sA0 = smem_u32(sA);
    const uint32_t sX0 = smem_u32(sX);

    float acc[2][4][4];
#pragma unroll
    for (int mt = 0; mt < 2; mt++)
#pragma unroll
        for (int nt = 0; nt < 4; nt++)
#pragma unroll
            for (int i = 0; i < 4; i++) acc[mt][nt][i] = 0.f;

    // ---- chunk loader ----
    auto load_chunk = [&](int cc) {
        const int pass = cc >> 2;
        const int k0 = (cc & 3) * 64;
        const __half* Ap = (pass == 2) ? Alo : Ahi;
        const __half* Xp = (pass == 1) ? Blo_b : Bhi_b;
        const int buf = cc & 1;
        uint32_t dA = sA0 + buf * 16384;
        uint32_t dX = sX0 + buf * 8192;
#pragma unroll
        for (int j = 0; j < 4; j++) {          // A: 1024 16B-chunks
            int idx = tid + j * 256;
            int row = idx >> 3, ch = idx & 7;
            cp16(dA + sw128(row * 128 + ch * 16), Ap + (size_t)(m0 + row) * CIN + k0 + ch * 8);
        }
#pragma unroll
        for (int j = 0; j < 2; j++) {          // X: 512 16B-chunks
            int idx = tid + j * 256;
            int row = idx >> 3, ch = idx & 7;
            cp16(dX + sw128(row * 128 + ch * 16), Xp + (size_t)(k0 + row) * LTOT + l0 + ch * 8);
        }
    };

    load_chunk(0);
    CP_COMMIT();

    for (int cc = 0; cc < 12; cc++) {
        if (cc + 1 < 12) {
            load_chunk(cc + 1);
            CP_COMMIT();
            CP_WAIT(1);
        } else {
            CP_WAIT(0);
        }
        __syncthreads();

        const int buf = cc & 1;
        const uint32_t sAb = sA0 + buf * 16384;
        const uint32_t sXb = sX0 + buf * 8192;
        const int b3 = lane >> 3, r8 = lane & 7;

#pragma unroll
        for (int kk = 0; kk < 4; kk++) {
            uint32_t afr[2][4];
#pragma unroll
            for (int mt = 0; mt < 2; mt++) {
                int row = m_base + mt * 16 + ((b3 & 1) << 3) + r8;
                int byte = row * 128 + kk * 32 + ((b3 >> 1) << 4);
                ldmA(afr[mt], sAb + sw128((uint32_t)byte));
            }
            uint32_t bfr[4][2];
#pragma unroll
            for (int nt = 0; nt < 4; nt++) {
                int krow = kk * 16 + (lane & 15);
                int byte = krow * 128 + (n_base + nt * 8) * 2;
                ldmBt(bfr[nt], sXb + sw128((uint32_t)byte));
            }
#pragma unroll
            for (int mt = 0; mt < 2; mt++)
#pragma unroll
                for (int nt = 0; nt < 4; nt++)
                    hmma(acc[mt][nt], afr[mt], bfr[nt]);
        }
        __syncthreads();
    }

    // ---- epilogue ----
    const int g = lane >> 2, j2 = (lane & 3) * 2;
    float* Cb = C + (size_t)b * DMODEL * LTOT;
#pragma unroll
    for (int mt = 0; mt < 2; mt++) {
        int mrow = m0 + m_base + mt * 16 + g;
#pragma unroll
        for (int nt = 0; nt < 4; nt++) {
            int col = l0 + n_base + nt * 8 + j2;
            *reinterpret_cast<float2*>(Cb + (size_t)mrow * LTOT + col) =
                make_float2(acc[mt][nt][0], acc[mt][nt][1]);
            *reinterpret_cast<float2*>(Cb + (size_t)(mrow + 8) * LTOT + col) =
                make_float2(acc[mt][nt][2], acc[mt][nt][3]);
        }
    }
}

// ---------------- K3: s[b,h,l] = sum_c wq[b,h,c] * x[b,c,l] ----------------
__global__ void s_kernel(const float* __restrict__ x) {
    __shared__ float wq_s[HEADS * CIN];
    const int b = blockIdx.y;
    for (int i = threadIdx.x; i < HEADS * CIN; i += 256)
        wq_s[i] = g_wq[b * HEADS * CIN + i];
    __syncthreads();
    int l = blockIdx.x * 256 + threadIdx.x;
    if (l >= LTOT) return;
    const float* xb = x + (size_t)b * CIN * LTOT;
    float acc[HEADS] = {};
    for (int c = 0; c < CIN; c++) {
        float xv = xb[(size_t)c * LTOT + l];
#pragma unroll
        for (int h = 0; h < HEADS; h++) acc[h] += wq_s[h * CIN + c] * xv;
    }
#pragma unroll
    for (int h = 0; h < HEADS; h++)
        g_s[(size_t)(b * HEADS + h) * LTOT + l] = acc[h];
}

// ---------------- K4: softmax over 9 taps + bias + Wlin scale ----------------
__global__ void attn_kernel(const float* __restrict__ pos_emb, const float* __restrict__ Wlin) {
    int bh = blockIdx.y;
    int l = blockIdx.x * 256 + threadIdx.x;
    if (l >= LTOT) return;
    float scale = Wlin[0] + Wlin[1] + Wlin[2] + Wlin[3];
    int y = l / HDIM, xx = l % HDIM;
    const float* sp = g_s + (size_t)bh * LTOT;
    float logit[KWIN];
#pragma unroll
    for (int kh = 0; kh < 3; kh++)
#pragma unroll
        for (int kw = 0; kw < 3; kw++) {
            int yy = y + kh - 1, xz = xx + kw - 1;
            float sv = (yy >= 0 && yy < HDIM && xz >= 0 && xz < HDIM) ? sp[yy * HDIM + xz] : 0.f;
            logit[kh * 3 + kw] = sv + pos_emb[kh + kw];
        }
    float m = logit[0];
#pragma unroll
    for (int k = 1; k < KWIN; k++) m = fmaxf(m, logit[k]);
    float e[KWIN], sum = 0.f;
#pragma unroll
    for (int k = 0; k < KWIN; k++) { e[k] = __expf(logit[k] - m); sum += e[k]; }
    float inv = scale / sum;
    float* ap = g_attn + (size_t)(bh * KWIN) * LTOT + l;
#pragma unroll
    for (int k = 0; k < KWIN; k++) ap[(size_t)k * LTOT] = e[k] * inv;
}

// ---------------- K5: out = sum_k attn * v(shifted), fused fp16 hi/lo split ----------------
__global__ void av_kernel() {
    int bd = blockIdx.y;
    int b = bd >> 8, d = bd & 255;
    int h = d >> 5;
    int l = blockIdx.x * 256 + threadIdx.x;
    if (l >= LTOT) return;
    int y = l / HDIM, xx = l % HDIM;
    const float* ap = g_attn + (size_t)((b * HEADS + h) * KWIN) * LTOT + l;
    const float* vp = g_v + (size_t)bd * LTOT;
    float acc = 0.f;
#pragma unroll
    for (int kh = 0; kh < 3; kh++) {
        int yy = y + kh - 1;
        if (yy < 0 || yy >= HDIM) continue;
#pragma unroll
        for (int kw = 0; kw < 3; kw++) {
            int xz = xx + kw - 1;
            if (xz < 0 || xz >= HDIM) continue;
            acc += ap[(size_t)(kh * 3 + kw) * LTOT] * vp[yy * HDIM + xz];
        }
    }
    size_t idx = (size_t)bd * LTOT + l;
    __half hi = __float2half(acc);
    g_ohi[idx] = hi;
    g_olo[idx] = __float2half(acc - __half2float(hi));
}

// ---------------- host launcher ----------------
extern "C" void kernel_launch(void* const* d_in, const int* in_sizes, int n_in,
                              void* d_out, int out_size) {
    const float* x       = (const float*)d_in[0];
    const float* q       = (const float*)d_in[1];
    const float* Wk      = (const float*)d_in[2];
    const float* Wv      = (const float*)d_in[3];
    const float* pos_emb = (const float*)d_in[4];
    const float* Wlin    = (const float*)d_in[5];
    const float* Wproj   = (const float*)d_in[6];
    float* out = (float*)d_out;

    void *pv, *pxhi, *pxlo, *pohi, *polo, *pwvhi, *pwvlo, *pwphi, *pwplo;
    cudaGetSymbolAddress(&pv, g_v);
    cudaGetSymbolAddress(&pxhi, g_xhi);
    cudaGetSymbolAddress(&pxlo, g_xlo);
    cudaGetSymbolAddress(&pohi, g_ohi);
    cudaGetSymbolAddress(&polo, g_olo);
    cudaGetSymbolAddress(&pwvhi, g_wvhi);
    cudaGetSymbolAddress(&pwvlo, g_wvlo);
    cudaGetSymbolAddress(&pwphi, g_wphi);
    cudaGetSymbolAddress(&pwplo, g_wplo);

    const int LBLKS = (LTOT + 255) / 256;
    const int XN4 = BATCH * CIN * LTOT / 4;
    const int WN4 = DMODEL * CIN / 4;

    wq_kernel<<<BATCH * HEADS, 256>>>(q, Wk);
    split_kernel<<<(XN4 + 255) / 256, 256>>>(x, (__half*)pxhi, (__half*)pxlo, XN4);
    split_kernel<<<(WN4 + 255) / 256, 256>>>(Wv, (__half*)pwvhi, (__half*)pwvlo, WN4);
    split_kernel<<<(WN4 + 255) / 256, 256>>>(Wproj, (__half*)pwphi, (__half*)pwplo, WN4);

    hgemm<<<dim3(LTOT / 64, DMODEL / 128, BATCH), 256>>>(
        (const __half*)pwvhi, (const __half*)pwvlo,
        (const __half*)pxhi, (const __half*)pxlo, (float*)pv);

    s_kernel<<<dim3(LBLKS, BATCH), 256>>>(x);
    attn_kernel<<<dim3(LBLKS, BATCH * HEADS), 256>>>(pos_emb, Wlin);
    av_kernel<<<dim3(LBLKS, BATCH * DMODEL), 256>>>();

    hgemm<<<dim3(LTOT / 64, DMODEL / 128, BATCH), 256>>>(
        (const __half*)pwphi, (const __half*)pwplo,
        (const __half*)pohi, (const __half*)polo, out);
}

// round 4
// speedup vs baseline: 1.9731x; 1.1374x over previous
#include <cuda_runtime.h>
#include <cuda_fp16.h>
#include <cstdint>

#define BATCH 16
#define CIN   256
#define DMODEL 256
#define HEADS 8
#define NPH   32
#define HDIM  56
#define LTOT  3136
#define KWIN  9

// ---------------- device scratch ----------------
__device__ float g_wq[BATCH * HEADS * CIN];
__device__ float g_s[BATCH * HEADS * LTOT];
__device__ float g_v[BATCH * DMODEL * LTOT];
__device__ float g_out[BATCH * DMODEL * LTOT];
__device__ float g_attn[BATCH * HEADS * KWIN * LTOT];
__device__ __align__(16) __half g_wvhi[DMODEL * CIN];
__device__ __align__(16) __half g_wvlo[DMODEL * CIN];
__device__ __align__(16) __half g_wphi[DMODEL * DMODEL];
__device__ __align__(16) __half g_wplo[DMODEL * DMODEL];

// ---------------- PTX helpers ----------------
__device__ __forceinline__ uint32_t smem_u32(const void* p) {
    uint32_t a;
    asm("{ .reg .u64 t; cvta.to.shared.u64 t, %1; cvt.u32.u64 %0, t; }" : "=r"(a) : "l"(p));
    return a;
}
__device__ __forceinline__ void ldmA4(uint32_t* r, uint32_t addr) {
    asm volatile("ldmatrix.sync.aligned.m8n8.x4.shared.b16 {%0,%1,%2,%3}, [%4];"
                 : "=r"(r[0]), "=r"(r[1]), "=r"(r[2]), "=r"(r[3]) : "r"(addr));
}
__device__ __forceinline__ void ldmBt4(uint32_t* r, uint32_t addr) {
    asm volatile("ldmatrix.sync.aligned.m8n8.x4.trans.shared.b16 {%0,%1,%2,%3}, [%4];"
                 : "=r"(r[0]), "=r"(r[1]), "=r"(r[2]), "=r"(r[3]) : "r"(addr));
}
__device__ __forceinline__ void hmma(float* d, const uint32_t* a, const uint32_t* b) {
    asm volatile("mma.sync.aligned.m16n8k16.row.col.f32.f16.f16.f32 "
                 "{%0,%1,%2,%3}, {%4,%5,%6,%7}, {%8,%9}, {%0,%1,%2,%3};"
                 : "+f"(d[0]), "+f"(d[1]), "+f"(d[2]), "+f"(d[3])
                 : "r"(a[0]), "r"(a[1]), "r"(a[2]), "r"(a[3]), "r"(b[0]), "r"(b[1]));
}
__device__ __forceinline__ void cp16(uint32_t dst, const void* src) {
    asm volatile("cp.async.cg.shared.global [%0], [%1], 16;" :: "r"(dst), "l"(src));
}
#define CP_COMMIT() asm volatile("cp.async.commit_group;" ::: "memory")
#define CP_WAIT0()  asm volatile("cp.async.wait_group 0;" ::: "memory")

__device__ __forceinline__ uint32_t sw128(uint32_t b) { return b ^ ((b >> 3) & 0x70); }

// ---------------- K0: hi/lo fp16 split (weights only) ----------------
__global__ void split_kernel(const float* __restrict__ src, __half* __restrict__ hi,
                             __half* __restrict__ lo, int n4) {
    int i = blockIdx.x * 256 + threadIdx.x;
    if (i >= n4) return;
    float4 v = reinterpret_cast<const float4*>(src)[i];
    float vv[4] = {v.x, v.y, v.z, v.w};
    __half h[4], l[4];
#pragma unroll
    for (int j = 0; j < 4; j++) {
        h[j] = __float2half(vv[j]);
        l[j] = __float2half(vv[j] - __half2float(h[j]));
    }
    __half2* H = reinterpret_cast<__half2*>(hi);
    __half2* L = reinterpret_cast<__half2*>(lo);
    H[2 * i]     = __half2(h[0], h[1]);
    H[2 * i + 1] = __half2(h[2], h[3]);
    L[2 * i]     = __half2(l[0], l[1]);
    L[2 * i + 1] = __half2(l[2], l[3]);
}

// ---------------- K1: wq[b,h,c] = sum_n q[b,h*32+n] * Wk[h*32+n, c] ----------------
__global__ void wq_kernel(const float* __restrict__ q, const float* __restrict__ Wk) {
    int bh = blockIdx.x;
    int b = bh >> 3, h = bh & 7;
    __shared__ float qs[NPH];
    if (threadIdx.x < NPH) qs[threadIdx.x] = q[b * DMODEL + h * NPH + threadIdx.x];
    __syncthreads();
    int c = threadIdx.x;
    float acc = 0.f;
#pragma unroll
    for (int n = 0; n < NPH; n++) acc += qs[n] * Wk[(h * NPH + n) * CIN + c];
    g_wq[bh * CIN + c] = acc;
}

// ---------------- K2: HMMA compensated GEMM, fp32 X input ----------------
// C[b,m,l] = sum_c A[m,c] * X[b,c,l];  A = Ahi+Alo (fp16 pair), X split in-kernel.
// CTA: M=128, N=64, K-chunks of 64 (4 chunks). 8 warps, 32x32 warp tiles.
// smem per stage (48KB): Ahi 16K | Alo 16K | Xhi 8K | Xlo 8K. Two stages.
#define STAGE_BYTES 49152
__global__ void __launch_bounds__(256, 2) hgemm(
    const __half* __restrict__ Ahi, const __half* __restrict__ Alo,
    const float* __restrict__ X, float* __restrict__ C) {
    extern __shared__ __align__(1024) unsigned char dsm[];
    unsigned char* sb = dsm;   // dynamic smem is suitably aligned; bank-swizzle only needs 128B
    const uint32_t s0 = smem_u32(sb);

    const int tid = threadIdx.x;
    const int wid = tid >> 5, lane = tid & 31;
    const int l0 = blockIdx.x * 64;
    const int m0 = blockIdx.y * 128;
    const int b  = blockIdx.z;

    const int m_base = (wid >> 1) * 32;
    const int n_base = (wid & 1) * 32;

    const float* Xb = X + (size_t)b * CIN * LTOT;

    float acc[2][4][4];
#pragma unroll
    for (int mt = 0; mt < 2; mt++)
#pragma unroll
        for (int nt = 0; nt < 4; nt++)
#pragma unroll
            for (int i = 0; i < 4; i++) acc[mt][nt][i] = 0.f;

    // A loader: chunk c into stage st (cp.async, 4 hi + 4 lo 16B per thread)
    auto loadA = [&](int c, int st) {
        const int k0 = c * 64;
        uint32_t dHi = s0 + st * STAGE_BYTES;
        uint32_t dLo = dHi + 16384;
#pragma unroll
        for (int j = 0; j < 4; j++) {
            int idx = tid + j * 256;
            int row = idx >> 3, ch = idx & 7;
            uint32_t off = sw128(row * 128 + ch * 16);
            size_t gidx = (size_t)(m0 + row) * CIN + k0 + ch * 8;
            cp16(dHi + off, Ahi + gidx);
            cp16(dLo + off, Alo + gidx);
        }
    };
    // X loader: LDG fp32 chunk into registers
    auto loadX = [&](int c, float4* xr) {
        const int k0 = c * 64;
#pragma unroll
        for (int j = 0; j < 4; j++) {
            int idx = tid + j * 256;
            int k = idx >> 4, nq = idx & 15;
            xr[j] = *reinterpret_cast<const float4*>(Xb + (size_t)(k0 + k) * LTOT + l0 + nq * 4);
        }
    };
    // X converter: regs -> swizzled smem hi/lo
    auto stsX = [&](int st, const float4* xr) {
        unsigned char* pHi = sb + st * STAGE_BYTES + 32768;
        unsigned char* pLo = pHi + 8192;
#pragma unroll
        for (int j = 0; j < 4; j++) {
            int idx = tid + j * 256;
            int k = idx >> 4, nq = idx & 15;
            float v0 = xr[j].x, v1 = xr[j].y, v2 = xr[j].z, v3 = xr[j].w;
            __half h0 = __float2half(v0), h1 = __float2half(v1);
            __half h2 = __float2half(v2), h3 = __float2half(v3);
            __half l0h = __float2half(v0 - __half2float(h0));
            __half l1h = __float2half(v1 - __half2float(h1));
            __half l2h = __float2half(v2 - __half2float(h2));
            __half l3h = __float2half(v3 - __half2float(h3));
            uint32_t off = sw128((uint32_t)(k * 128 + nq * 8));
            __half2 hh[2] = {__half2(h0, h1), __half2(h2, h3)};
            __half2 ll[2] = {__half2(l0h, l1h), __half2(l2h, l3h)};
            *reinterpret_cast<uint2*>(pHi + off) = *reinterpret_cast<uint2*>(hh);
            *reinterpret_cast<uint2*>(pLo + off) = *reinterpret_cast<uint2*>(ll);
        }
    };

    float4 xr[4];
    loadA(0, 0);
    CP_COMMIT();
    loadX(0, xr);
    stsX(0, xr);
    CP_WAIT0();
    __syncthreads();

    const int b3 = lane >> 3, r8 = lane & 7;

    for (int c = 0; c < 4; c++) {
        const int st = c & 1;
        if (c + 1 < 4) {
            loadA(c + 1, st ^ 1);
            CP_COMMIT();
            loadX(c + 1, xr);
        }

        const uint32_t sAhi = s0 + st * STAGE_BYTES;
        const uint32_t sAlo = sAhi + 16384;
        const uint32_t sXhi = sAhi + 32768;
        const uint32_t sXlo = sAhi + 40960;

#pragma unroll
        for (int kk = 0; kk < 4; kk++) {
            uint32_t ahi[2][4], alo[2][4], bhi[2][4], blo[2][4];
#pragma unroll
            for (int mt = 0; mt < 2; mt++) {
                int row = m_base + mt * 16 + ((b3 & 1) << 3) + r8;
                uint32_t byte = sw128((uint32_t)(row * 128 + kk * 32 + ((b3 >> 1) << 4)));
                ldmA4(ahi[mt], sAhi + byte);
                ldmA4(alo[mt], sAlo + byte);
            }
#pragma unroll
            for (int g = 0; g < 2; g++) {
                int krow = kk * 16 + (lane & 15);
                int ncol = n_base + g * 16 + ((lane >> 4) << 3);
                uint32_t byte = sw128((uint32_t)(krow * 128 + ncol * 2));
                ldmBt4(bhi[g], sXhi + byte);
                ldmBt4(blo[g], sXlo + byte);
            }
#pragma unroll
            for (int mt = 0; mt < 2; mt++)
#pragma unroll
                for (int g = 0; g < 2; g++)
#pragma unroll
                    for (int h = 0; h < 2; h++) {
                        float* a = acc[mt][g * 2 + h];
                        hmma(a, ahi[mt], &bhi[g][h * 2]);   // hh
                        hmma(a, ahi[mt], &blo[g][h * 2]);   // hl
                        hmma(a, alo[mt], &bhi[g][h * 2]);   // lh
                    }
        }

        if (c + 1 < 4) {
            stsX(st ^ 1, xr);
            CP_WAIT0();
        }
        __syncthreads();
    }

    // ---- epilogue ----
    const int g = lane >> 2, j2 = (lane & 3) * 2;
    float* Cb = C + (size_t)b * DMODEL * LTOT;
#pragma unroll
    for (int mt = 0; mt < 2; mt++) {
        int mrow = m0 + m_base + mt * 16 + g;
#pragma unroll
        for (int nt = 0; nt < 4; nt++) {
            int col = l0 + n_base + nt * 8 + j2;
            *reinterpret_cast<float2*>(Cb + (size_t)mrow * LTOT + col) =
                make_float2(acc[mt][nt][0], acc[mt][nt][1]);
            *reinterpret_cast<float2*>(Cb + (size_t)(mrow + 8) * LTOT + col) =
                make_float2(acc[mt][nt][2], acc[mt][nt][3]);
        }
    }
}

// ---------------- K3: s[b,h,l] = sum_c wq[b,h,c] * x[b,c,l] ----------------
__global__ void s_kernel(const float* __restrict__ x) {
    __shared__ float wq_s[HEADS * CIN];
    const int b = blockIdx.y;
    for (int i = threadIdx.x; i < HEADS * CIN; i += 256)
        wq_s[i] = g_wq[b * HEADS * CIN + i];
    __syncthreads();
    int l = blockIdx.x * 256 + threadIdx.x;
    if (l >= LTOT) return;
    const float* xb = x + (size_t)b * CIN * LTOT;
    float acc[HEADS] = {};
    for (int c = 0; c < CIN; c++) {
        float xv = xb[(size_t)c * LTOT + l];
#pragma unroll
        for (int h = 0; h < HEADS; h++) acc[h] += wq_s[h * CIN + c] * xv;
    }
#pragma unroll
    for (int h = 0; h < HEADS; h++)
        g_s[(size_t)(b * HEADS + h) * LTOT + l] = acc[h];
}

// ---------------- K4: softmax over 9 taps + bias + Wlin scale ----------------
__global__ void attn_kernel(const float* __restrict__ pos_emb, const float* __restrict__ Wlin) {
    int bh = blockIdx.y;
    int l = blockIdx.x * 256 + threadIdx.x;
    if (l >= LTOT) return;
    float scale = Wlin[0] + Wlin[1] + Wlin[2] + Wlin[3];
    int y = l / HDIM, xx = l % HDIM;
    const float* sp = g_s + (size_t)bh * LTOT;
    float logit[KWIN];
#pragma unroll
    for (int kh = 0; kh < 3; kh++)
#pragma unroll
        for (int kw = 0; kw < 3; kw++) {
            int yy = y + kh - 1, xz = xx + kw - 1;
            float sv = (yy >= 0 && yy < HDIM && xz >= 0 && xz < HDIM) ? sp[yy * HDIM + xz] : 0.f;
            logit[kh * 3 + kw] = sv + pos_emb[kh + kw];
        }
    float m = logit[0];
#pragma unroll
    for (int k = 1; k < KWIN; k++) m = fmaxf(m, logit[k]);
    float e[KWIN], sum = 0.f;
#pragma unroll
    for (int k = 0; k < KWIN; k++) { e[k] = __expf(logit[k] - m); sum += e[k]; }
    float inv = scale / sum;
    float* ap = g_attn + (size_t)(bh * KWIN) * LTOT + l;
#pragma unroll
    for (int k = 0; k < KWIN; k++) ap[(size_t)k * LTOT] = e[k] * inv;
}

// ---------------- K5: out[b,d,l] = sum_k attn * v(shifted) ----------------
__global__ void av_kernel() {
    int bd = blockIdx.y;
    int b = bd >> 8, d = bd & 255;
    int h = d >> 5;
    int l = blockIdx.x * 256 + threadIdx.x;
    if (l >= LTOT) return;
    int y = l / HDIM, xx = l % HDIM;
    const float* ap = g_attn + (size_t)((b * HEADS + h) * KWIN) * LTOT + l;
    const float* vp = g_v + (size_t)bd * LTOT;
    float acc = 0.f;
#pragma unroll
    for (int kh = 0; kh < 3; kh++) {
        int yy = y + kh - 1;
        if (yy < 0 || yy >= HDIM) continue;
#pragma unroll
        for (int kw = 0; kw < 3; kw++) {
            int xz = xx + kw - 1;
            if (xz < 0 || xz >= HDIM) continue;
            acc += ap[(size_t)(kh * 3 + kw) * LTOT] * vp[yy * HDIM + xz];
        }
    }
    g_out[(size_t)bd * LTOT + l] = acc;
}

// ---------------- host launcher ----------------
extern "C" void kernel_launch(void* const* d_in, const int* in_sizes, int n_in,
                              void* d_out, int out_size) {
    const float* x       = (const float*)d_in[0];
    const float* q       = (const float*)d_in[1];
    const float* Wk      = (const float*)d_in[2];
    const float* Wv      = (const float*)d_in[3];
    const float* pos_emb = (const float*)d_in[4];
    const float* Wlin    = (const float*)d_in[5];
    const float* Wproj   = (const float*)d_in[6];
    float* out = (float*)d_out;

    void *pv, *pout, *pwvhi, *pwvlo, *pwphi, *pwplo;
    cudaGetSymbolAddress(&pv, g_v);
    cudaGetSymbolAddress(&pout, g_out);
    cudaGetSymbolAddress(&pwvhi, g_wvhi);
    cudaGetSymbolAddress(&pwvlo, g_wvlo);
    cudaGetSymbolAddress(&pwphi, g_wphi);
    cudaGetSymbolAddress(&pwplo, g_wplo);

    static bool attr_set = false;
    if (!attr_set) {
        cudaFuncSetAttribute(hgemm, cudaFuncAttributeMaxDynamicSharedMemorySize,
                             2 * STAGE_BYTES);
        attr_set = true;
    }

    const int LBLKS = (LTOT + 255) / 256;
    const int WN4 = DMODEL * CIN / 4;
    const int SMEM = 2 * STAGE_BYTES;

    wq_kernel<<<BATCH * HEADS, 256>>>(q, Wk);
    split_kernel<<<(WN4 + 255) / 256, 256>>>(Wv, (__half*)pwvhi, (__half*)pwvlo, WN4);
    split_kernel<<<(WN4 + 255) / 256, 256>>>(Wproj, (__half*)pwphi, (__half*)pwplo, WN4);

    hgemm<<<dim3(LTOT / 64, DMODEL / 128, BATCH), 256, SMEM>>>(
        (const __half*)pwvhi, (const __half*)pwvlo, x, (float*)pv);

    s_kernel<<<dim3(LBLKS, BATCH), 256>>>(x);
    attn_kernel<<<dim3(LBLKS, BATCH * HEADS), 256>>>(pos_emb, Wlin);
    av_kernel<<<dim3(LBLKS, BATCH * DMODEL), 256>>>();

    hgemm<<<dim3(LTOT / 64, DMODEL / 128, BATCH), 256, SMEM>>>(
        (const __half*)pwphi, (const __half*)pwplo, (const float*)pout, out);
}

// round 5
// speedup vs baseline: 2.0679x; 1.0480x over previous
#include <cuda_runtime.h>
#include <cuda_fp16.h>
#include <cstdint>

#define BATCH 16
#define CIN   256
#define DMODEL 256
#define HEADS 8
#define NPH   32
#define HDIM  56
#define LTOT  3136
#define KWIN  9

// ---------------- device scratch ----------------
__device__ float g_wq[BATCH * HEADS * CIN];
__device__ float g_s[BATCH * HEADS * LTOT];
__device__ float g_v[BATCH * DMODEL * LTOT];
__device__ float g_attn[BATCH * HEADS * KWIN * LTOT];
__device__ __align__(16) __half g_xhi[BATCH * CIN * LTOT];
__device__ __align__(16) __half g_xlo[BATCH * CIN * LTOT];
__device__ __align__(16) __half g_ohi[BATCH * DMODEL * LTOT];
__device__ __align__(16) __half g_olo[BATCH * DMODEL * LTOT];
__device__ __align__(16) __half g_wvhi[DMODEL * CIN];
__device__ __align__(16) __half g_wvlo[DMODEL * CIN];
__device__ __align__(16) __half g_wphi[DMODEL * DMODEL];
__device__ __align__(16) __half g_wplo[DMODEL * DMODEL];

// ---------------- PTX helpers ----------------
__device__ __forceinline__ uint32_t smem_u32(const void* p) {
    uint32_t a;
    asm("{ .reg .u64 t; cvta.to.shared.u64 t, %1; cvt.u32.u64 %0, t; }" : "=r"(a) : "l"(p));
    return a;
}
__device__ __forceinline__ void ldmA4(uint32_t* r, uint32_t addr) {
    asm volatile("ldmatrix.sync.aligned.m8n8.x4.shared.b16 {%0,%1,%2,%3}, [%4];"
                 : "=r"(r[0]), "=r"(r[1]), "=r"(r[2]), "=r"(r[3]) : "r"(addr));
}
__device__ __forceinline__ void ldmBt4(uint32_t* r, uint32_t addr) {
    asm volatile("ldmatrix.sync.aligned.m8n8.x4.trans.shared.b16 {%0,%1,%2,%3}, [%4];"
                 : "=r"(r[0]), "=r"(r[1]), "=r"(r[2]), "=r"(r[3]) : "r"(addr));
}
__device__ __forceinline__ void hmma(float* d, const uint32_t* a, const uint32_t* b) {
    asm volatile("mma.sync.aligned.m16n8k16.row.col.f32.f16.f16.f32 "
                 "{%0,%1,%2,%3}, {%4,%5,%6,%7}, {%8,%9}, {%0,%1,%2,%3};"
                 : "+f"(d[0]), "+f"(d[1]), "+f"(d[2]), "+f"(d[3])
                 : "r"(a[0]), "r"(a[1]), "r"(a[2]), "r"(a[3]), "r"(b[0]), "r"(b[1]));
}
__device__ __forceinline__ void cp16(uint32_t dst, const void* src) {
    asm volatile("cp.async.cg.shared.global [%0], [%1], 16;" :: "r"(dst), "l"(src));
}
#define CP_COMMIT() asm volatile("cp.async.commit_group;" ::: "memory")
__device__ __forceinline__ uint32_t sw128(uint32_t b) { return b ^ ((b >> 3) & 0x70); }

// ---------------- K0: hi/lo fp16 split (weights) ----------------
__global__ void split_kernel(const float* __restrict__ src, __half* __restrict__ hi,
                             __half* __restrict__ lo, int n4) {
    int i = blockIdx.x * 256 + threadIdx.x;
    if (i >= n4) return;
    float4 v = reinterpret_cast<const float4*>(src)[i];
    float vv[4] = {v.x, v.y, v.z, v.w};
    __half h[4], l[4];
#pragma unroll
    for (int j = 0; j < 4; j++) {
        h[j] = __float2half(vv[j]);
        l[j] = __float2half(vv[j] - __half2float(h[j]));
    }
    __half2* H = reinterpret_cast<__half2*>(hi);
    __half2* L = reinterpret_cast<__half2*>(lo);
    H[2 * i]     = __half2(h[0], h[1]);
    H[2 * i + 1] = __half2(h[2], h[3]);
    L[2 * i]     = __half2(l[0], l[1]);
    L[2 * i + 1] = __half2(l[2], l[3]);
}

// ---------------- K1: wq[b,h,c] = sum_n q[b,h*32+n] * Wk[h*32+n, c] ----------------
__global__ void wq_kernel(const float* __restrict__ q, const float* __restrict__ Wk) {
    int bh = blockIdx.x;
    int b = bh >> 3, h = bh & 7;
    __shared__ float qs[NPH];
    if (threadIdx.x < NPH) qs[threadIdx.x] = q[b * DMODEL + h * NPH + threadIdx.x];
    __syncthreads();
    int c = threadIdx.x;
    float acc = 0.f;
#pragma unroll
    for (int n = 0; n < NPH; n++) acc += qs[n] * Wk[(h * NPH + n) * CIN + c];
    g_wq[bh * CIN + c] = acc;
}

// ---------------- K2: s + x hi/lo split fused ----------------
// grid (49, 16), block 256 = 64 l x 4 c-split
__global__ void __launch_bounds__(256) s_split_kernel(const float* __restrict__ x) {
    __shared__ float wq_s[HEADS * CIN];         // 8 KB
    __shared__ float red[4][HEADS][64];         // 8 KB
    const int b = blockIdx.y;
    for (int i = threadIdx.x; i < HEADS * CIN; i += 256)
        wq_s[i] = g_wq[b * HEADS * CIN + i];
    __syncthreads();

    const int li = threadIdx.x & 63;
    const int cs = threadIdx.x >> 6;
    const int l = blockIdx.x * 64 + li;
    const float* xb = x + (size_t)b * CIN * LTOT;
    __half* xhi = g_xhi + (size_t)b * CIN * LTOT;
    __half* xlo = g_xlo + (size_t)b * CIN * LTOT;

    float acc[HEADS] = {};
#pragma unroll 4
    for (int cc = 0; cc < 64; cc++) {
        int c = cs * 64 + cc;
        float v = xb[(size_t)c * LTOT + l];
        __half h = __float2half(v);
        xhi[(size_t)c * LTOT + l] = h;
        xlo[(size_t)c * LTOT + l] = __float2half(v - __half2float(h));
#pragma unroll
        for (int hh = 0; hh < HEADS; hh++) acc[hh] += wq_s[hh * CIN + c] * v;
    }
#pragma unroll
    for (int hh = 0; hh < HEADS; hh++) red[cs][hh][li] = acc[hh];
    __syncthreads();
    for (int i = threadIdx.x; i < HEADS * 64; i += 256) {
        int hh = i >> 6, l2 = i & 63;
        float s = red[0][hh][l2] + red[1][hh][l2] + red[2][hh][l2] + red[3][hh][l2];
        g_s[(size_t)(b * HEADS + hh) * LTOT + blockIdx.x * 64 + l2] = s;
    }
}

// ---------------- K3: HMMA compensated GEMM, all-fp16 cp.async feed ----------------
// C[b,m,l] = sum_c A[m,c]*X[b,c,l]; A,X given as hi/lo fp16 pairs.
// CTA: M=128, N=64; 4 K-chunks of 64; 8 warps of 32x32.
// stage (48KB): Ahi 16K | Alo 16K | Xhi 8K | Xlo 8K; two stages.
#define STAGE_BYTES 49152
__global__ void __launch_bounds__(256, 2) hgemm(
    const __half* __restrict__ Ahi, const __half* __restrict__ Alo,
    const __half* __restrict__ Xhi, const __half* __restrict__ Xlo,
    float* __restrict__ C) {
    extern __shared__ __align__(1024) unsigned char sb[];
    const uint32_t s0 = smem_u32(sb);

    const int tid = threadIdx.x;
    const int wid = tid >> 5, lane = tid & 31;
    const int l0 = blockIdx.x * 64;
    const int m0 = blockIdx.y * 128;
    const int b  = blockIdx.z;

    const int m_base = (wid >> 1) * 32;
    const int n_base = (wid & 1) * 32;

    const __half* Xhi_b = Xhi + (size_t)b * CIN * LTOT;
    const __half* Xlo_b = Xlo + (size_t)b * CIN * LTOT;

    float acc[2][4][4];
#pragma unroll
    for (int mt = 0; mt < 2; mt++)
#pragma unroll
        for (int nt = 0; nt < 4; nt++)
#pragma unroll
            for (int i = 0; i < 4; i++) acc[mt][nt][i] = 0.f;

    auto load_chunk = [&](int c) {
        const int st = c & 1;
        const int k0 = c * 64;
        uint32_t dAhi = s0 + st * STAGE_BYTES;
        uint32_t dAlo = dAhi + 16384;
        uint32_t dXhi = dAhi + 32768;
        uint32_t dXlo = dAhi + 40960;
#pragma unroll
        for (int j = 0; j < 4; j++) {      // A: 128 rows x 64k halves
            int idx = tid + j * 256;
            int row = idx >> 3, ch = idx & 7;
            uint32_t off = sw128(row * 128 + ch * 16);
            size_t gidx = (size_t)(m0 + row) * CIN + k0 + ch * 8;
            cp16(dAhi + off, Ahi + gidx);
            cp16(dAlo + off, Alo + gidx);
        }
#pragma unroll
        for (int j = 0; j < 2; j++) {      // X: 64 rows x 64n halves
            int idx = tid + j * 256;
            int row = idx >> 3, ch = idx & 7;
            uint32_t off = sw128(row * 128 + ch * 16);
            size_t gidx = (size_t)(k0 + row) * LTOT + l0 + ch * 8;
            cp16(dXhi + off, Xhi_b + gidx);
            cp16(dXlo + off, Xlo_b + gidx);
        }
        CP_COMMIT();
    };

    load_chunk(0);
    const int b3 = lane >> 3, r8 = lane & 7;

    for (int c = 0; c < 4; c++) {
        if (c + 1 < 4) {
            load_chunk(c + 1);
            asm volatile("cp.async.wait_group 1;" ::: "memory");
        } else {
            asm volatile("cp.async.wait_group 0;" ::: "memory");
        }
        __syncthreads();

        const int st = c & 1;
        const uint32_t sAhi = s0 + st * STAGE_BYTES;
        const uint32_t sAlo = sAhi + 16384;
        const uint32_t sXhi = sAhi + 32768;
        const uint32_t sXlo = sAhi + 40960;

#pragma unroll
        for (int kk = 0; kk < 4; kk++) {
            uint32_t ahi[2][4], alo[2][4], bhi[2][4], blo[2][4];
#pragma unroll
            for (int mt = 0; mt < 2; mt++) {
                int row = m_base + mt * 16 + ((b3 & 1) << 3) + r8;
                uint32_t byte = sw128((uint32_t)(row * 128 + kk * 32 + ((b3 >> 1) << 4)));
                ldmA4(ahi[mt], sAhi + byte);
                ldmA4(alo[mt], sAlo + byte);
            }
#pragma unroll
            for (int g = 0; g < 2; g++) {
                int krow = kk * 16 + (lane & 15);
                int ncol = n_base + g * 16 + ((lane >> 4) << 3);
                uint32_t byte = sw128((uint32_t)(krow * 128 + ncol * 2));
                ldmBt4(bhi[g], sXhi + byte);
                ldmBt4(blo[g], sXlo + byte);
            }
#pragma unroll
            for (int mt = 0; mt < 2; mt++)
#pragma unroll
                for (int g = 0; g < 2; g++)
#pragma unroll
                    for (int h = 0; h < 2; h++) {
                        float* a = acc[mt][g * 2 + h];
                        hmma(a, ahi[mt], &bhi[g][h * 2]);   // hh
                        hmma(a, ahi[mt], &blo[g][h * 2]);   // hl
                        hmma(a, alo[mt], &bhi[g][h * 2]);   // lh
                    }
        }
        __syncthreads();
    }

    // ---- epilogue ----
    const int g = lane >> 2, j2 = (lane & 3) * 2;
    float* Cb = C + (size_t)b * DMODEL * LTOT;
#pragma unroll
    for (int mt = 0; mt < 2; mt++) {
        int mrow = m0 + m_base + mt * 16 + g;
#pragma unroll
        for (int nt = 0; nt < 4; nt++) {
            int col = l0 + n_base + nt * 8 + j2;
            *reinterpret_cast<float2*>(Cb + (size_t)mrow * LTOT + col) =
                make_float2(acc[mt][nt][0], acc[mt][nt][1]);
            *reinterpret_cast<float2*>(Cb + (size_t)(mrow + 8) * LTOT + col) =
                make_float2(acc[mt][nt][2], acc[mt][nt][3]);
        }
    }
}

// ---------------- K4: softmax over 9 taps + bias + Wlin scale ----------------
__global__ void attn_kernel(const float* __restrict__ pos_emb, const float* __restrict__ Wlin) {
    int bh = blockIdx.y;
    int l = blockIdx.x * 256 + threadIdx.x;
    if (l >= LTOT) return;
    float scale = Wlin[0] + Wlin[1] + Wlin[2] + Wlin[3];
    int y = l / HDIM, xx = l % HDIM;
    const float* sp = g_s + (size_t)bh * LTOT;
    float logit[KWIN];
#pragma unroll
    for (int kh = 0; kh < 3; kh++)
#pragma unroll
        for (int kw = 0; kw < 3; kw++) {
            int yy = y + kh - 1, xz = xx + kw - 1;
            float sv = (yy >= 0 && yy < HDIM && xz >= 0 && xz < HDIM) ? sp[yy * HDIM + xz] : 0.f;
            logit[kh * 3 + kw] = sv + pos_emb[kh + kw];
        }
    float m = logit[0];
#pragma unroll
    for (int k = 1; k < KWIN; k++) m = fmaxf(m, logit[k]);
    float e[KWIN], sum = 0.f;
#pragma unroll
    for (int k = 0; k < KWIN; k++) { e[k] = __expf(logit[k] - m); sum += e[k]; }
    float inv = scale / sum;
    float* ap = g_attn + (size_t)(bh * KWIN) * LTOT + l;
#pragma unroll
    for (int k = 0; k < KWIN; k++) ap[(size_t)k * LTOT] = e[k] * inv;
}

// ---------------- K5: out = sum_k attn * v(shifted), writes fp16 hi/lo ----------------
__global__ void av_kernel() {
    int bd = blockIdx.y;
    int b = bd >> 8, d = bd & 255;
    int h = d >> 5;
    int l = blockIdx.x * 256 + threadIdx.x;
    if (l >= LTOT) return;
    int y = l / HDIM, xx = l % HDIM;
    const float* ap = g_attn + (size_t)((b * HEADS + h) * KWIN) * LTOT + l;
    const float* vp = g_v + (size_t)bd * LTOT;
    float acc = 0.f;
#pragma unroll
    for (int kh = 0; kh < 3; kh++) {
        int yy = y + kh - 1;
        if (yy < 0 || yy >= HDIM) continue;
#pragma unroll
        for (int kw = 0; kw < 3; kw++) {
            int xz = xx + kw - 1;
            if (xz < 0 || xz >= HDIM) continue;
            acc += ap[(size_t)(kh * 3 + kw) * LTOT] * vp[yy * HDIM + xz];
        }
    }
    size_t idx = (size_t)bd * LTOT + l;
    __half hi = __float2half(acc);
    g_ohi[idx] = hi;
    g_olo[idx] = __float2half(acc - __half2float(hi));
}

// ---------------- host launcher ----------------
extern "C" void kernel_launch(void* const* d_in, const int* in_sizes, int n_in,
                              void* d_out, int out_size) {
    const float* x       = (const float*)d_in[0];
    const float* q       = (const float*)d_in[1];
    const float* Wk      = (const float*)d_in[2];
    const float* Wv      = (const float*)d_in[3];
    const float* pos_emb = (const float*)d_in[4];
    const float* Wlin    = (const float*)d_in[5];
    const float* Wproj   = (const float*)d_in[6];
    float* out = (float*)d_out;

    void *pv, *pxhi, *pxlo, *pohi, *polo, *pwvhi, *pwvlo, *pwphi, *pwplo;
    cudaGetSymbolAddress(&pv, g_v);
    cudaGetSymbolAddress(&pxhi, g_xhi);
    cudaGetSymbolAddress(&pxlo, g_xlo);
    cudaGetSymbolAddress(&pohi, g_ohi);
    cudaGetSymbolAddress(&polo, g_olo);
    cudaGetSymbolAddress(&pwvhi, g_wvhi);
    cudaGetSymbolAddress(&pwvlo, g_wvlo);
    cudaGetSymbolAddress(&pwphi, g_wphi);
    cudaGetSymbolAddress(&pwplo, g_wplo);

    static bool attr_set = false;
    if (!attr_set) {
        cudaFuncSetAttribute(hgemm, cudaFuncAttributeMaxDynamicSharedMemorySize,
                             2 * STAGE_BYTES);
        attr_set = true;
    }

    const int LBLKS = (LTOT + 255) / 256;
    const int WN4 = DMODEL * CIN / 4;
    const int SMEM = 2 * STAGE_BYTES;

    wq_kernel<<<BATCH * HEADS, 256>>>(q, Wk);
    split_kernel<<<(WN4 + 255) / 256, 256>>>(Wv, (__half*)pwvhi, (__half*)pwvlo, WN4);
    split_kernel<<<(WN4 + 255) / 256, 256>>>(Wproj, (__half*)pwphi, (__half*)pwplo, WN4);
    s_split_kernel<<<dim3(LTOT / 64, BATCH), 256>>>(x);

    hgemm<<<dim3(LTOT / 64, DMODEL / 128, BATCH), 256, SMEM>>>(
        (const __half*)pwvhi, (const __half*)pwvlo,
        (const __half*)pxhi, (const __half*)pxlo, (float*)pv);

    attn_kernel<<<dim3(LBLKS, BATCH * HEADS), 256>>>(pos_emb, Wlin);
    av_kernel<<<dim3(LBLKS, BATCH * DMODEL), 256>>>();

    hgemm<<<dim3(LTOT / 64, DMODEL / 128, BATCH), 256, SMEM>>>(
        (const __half*)pwphi, (const __half*)pwplo,
        (const __half*)pohi, (const __half*)polo, out);
}

// round 6
// speedup vs baseline: 2.3020x; 1.1132x over previous
#include <cuda_runtime.h>
#include <cuda_fp16.h>
#include <cstdint>

#define BATCH 16
#define CIN   256
#define DMODEL 256
#define HEADS 8
#define NPH   32
#define HDIM  56
#define LTOT  3136
#define KWIN  9

// ---------------- device scratch ----------------
__device__ float g_wq[BATCH * HEADS * CIN];
__device__ float g_s[BATCH * HEADS * LTOT];
__device__ float g_v[BATCH * DMODEL * LTOT];
__device__ __align__(16) __half g_xhi[BATCH * CIN * LTOT];
__device__ __align__(16) __half g_xlo[BATCH * CIN * LTOT];
__device__ __align__(16) __half g_ohi[BATCH * DMODEL * LTOT];
__device__ __align__(16) __half g_olo[BATCH * DMODEL * LTOT];
__device__ __align__(16) __half g_wvhi[DMODEL * CIN];
__device__ __align__(16) __half g_wvlo[DMODEL * CIN];
__device__ __align__(16) __half g_wphi[DMODEL * DMODEL];
__device__ __align__(16) __half g_wplo[DMODEL * DMODEL];

// ---------------- PTX helpers ----------------
__device__ __forceinline__ uint32_t smem_u32(const void* p) {
    uint32_t a;
    asm("{ .reg .u64 t; cvta.to.shared.u64 t, %1; cvt.u32.u64 %0, t; }" : "=r"(a) : "l"(p));
    return a;
}
__device__ __forceinline__ void ldmA4(uint32_t* r, uint32_t addr) {
    asm volatile("ldmatrix.sync.aligned.m8n8.x4.shared.b16 {%0,%1,%2,%3}, [%4];"
                 : "=r"(r[0]), "=r"(r[1]), "=r"(r[2]), "=r"(r[3]) : "r"(addr));
}
__device__ __forceinline__ void ldmBt4(uint32_t* r, uint32_t addr) {
    asm volatile("ldmatrix.sync.aligned.m8n8.x4.trans.shared.b16 {%0,%1,%2,%3}, [%4];"
                 : "=r"(r[0]), "=r"(r[1]), "=r"(r[2]), "=r"(r[3]) : "r"(addr));
}
__device__ __forceinline__ void hmma(float* d, const uint32_t* a, const uint32_t* b) {
    asm volatile("mma.sync.aligned.m16n8k16.row.col.f32.f16.f16.f32 "
                 "{%0,%1,%2,%3}, {%4,%5,%6,%7}, {%8,%9}, {%0,%1,%2,%3};"
                 : "+f"(d[0]), "+f"(d[1]), "+f"(d[2]), "+f"(d[3])
                 : "r"(a[0]), "r"(a[1]), "r"(a[2]), "r"(a[3]), "r"(b[0]), "r"(b[1]));
}
__device__ __forceinline__ void cp16(uint32_t dst, const void* src) {
    asm volatile("cp.async.cg.shared.global [%0], [%1], 16;" :: "r"(dst), "l"(src));
}
#define CP_COMMIT() asm volatile("cp.async.commit_group;" ::: "memory")
__device__ __forceinline__ uint32_t sw128(uint32_t b) { return b ^ ((b >> 3) & 0x70); }

// ---------------- K0: hi/lo fp16 split (weights) ----------------
__global__ void split_kernel(const float* __restrict__ src, __half* __restrict__ hi,
                             __half* __restrict__ lo, int n4) {
    int i = blockIdx.x * 256 + threadIdx.x;
    if (i >= n4) return;
    float4 v = reinterpret_cast<const float4*>(src)[i];
    float vv[4] = {v.x, v.y, v.z, v.w};
    __half h[4], l[4];
#pragma unroll
    for (int j = 0; j < 4; j++) {
        h[j] = __float2half(vv[j]);
        l[j] = __float2half(vv[j] - __half2float(h[j]));
    }
    __half2* H = reinterpret_cast<__half2*>(hi);
    __half2* L = reinterpret_cast<__half2*>(lo);
    H[2 * i]     = __half2(h[0], h[1]);
    H[2 * i + 1] = __half2(h[2], h[3]);
    L[2 * i]     = __half2(l[0], l[1]);
    L[2 * i + 1] = __half2(l[2], l[3]);
}

// ---------------- K1: wq[b,h,c] = sum_n q[b,h*32+n] * Wk[h*32+n, c] ----------------
__global__ void wq_kernel(const float* __restrict__ q, const float* __restrict__ Wk) {
    int bh = blockIdx.x;
    int b = bh >> 3, h = bh & 7;
    __shared__ float qs[NPH];
    if (threadIdx.x < NPH) qs[threadIdx.x] = q[b * DMODEL + h * NPH + threadIdx.x];
    __syncthreads();
    int c = threadIdx.x;
    float acc = 0.f;
#pragma unroll
    for (int n = 0; n < NPH; n++) acc += qs[n] * Wk[(h * NPH + n) * CIN + c];
    g_wq[bh * CIN + c] = acc;
}

// ---------------- K2: s + x hi/lo split fused (vectorized) ----------------
// grid (49, 16), block 256 = 32 l-pairs x 8 c-splits
__global__ void __launch_bounds__(256) s_split_kernel(const float* __restrict__ x) {
    __shared__ float wq_s[HEADS * CIN];         // 8 KB
    __shared__ float red[8][HEADS][64];         // 16 KB
    const int b = blockIdx.y;
    for (int i = threadIdx.x; i < HEADS * CIN; i += 256)
        wq_s[i] = g_wq[b * HEADS * CIN + i];
    __syncthreads();

    const int lp = threadIdx.x & 31;            // l-pair index
    const int cs = threadIdx.x >> 5;            // 0..7
    const int l = blockIdx.x * 64 + lp * 2;
    const float* xb = x + (size_t)b * CIN * LTOT;
    __half* xhi = g_xhi + (size_t)b * CIN * LTOT;
    __half* xlo = g_xlo + (size_t)b * CIN * LTOT;

    float acc[HEADS][2] = {};
#pragma unroll 4
    for (int cc = 0; cc < 32; cc++) {
        int c = cs * 32 + cc;
        size_t idx = (size_t)c * LTOT + l;
        float2 v = *reinterpret_cast<const float2*>(xb + idx);
        __half2 h2 = __float22half2_rn(v);
        float2 hr = __half22float2(h2);
        __half2 l2 = __float22half2_rn(make_float2(v.x - hr.x, v.y - hr.y));
        *reinterpret_cast<__half2*>(xhi + idx) = h2;
        *reinterpret_cast<__half2*>(xlo + idx) = l2;
#pragma unroll
        for (int hh = 0; hh < HEADS; hh++) {
            float w = wq_s[hh * CIN + c];
            acc[hh][0] += w * v.x;
            acc[hh][1] += w * v.y;
        }
    }
#pragma unroll
    for (int hh = 0; hh < HEADS; hh++) {
        red[cs][hh][lp * 2]     = acc[hh][0];
        red[cs][hh][lp * 2 + 1] = acc[hh][1];
    }
    __syncthreads();
    for (int i = threadIdx.x; i < HEADS * 64; i += 256) {
        int hh = i >> 6, l2i = i & 63;
        float s = 0.f;
#pragma unroll
        for (int c8 = 0; c8 < 8; c8++) s += red[c8][hh][l2i];
        g_s[(size_t)(b * HEADS + hh) * LTOT + blockIdx.x * 64 + l2i] = s;
    }
}

// ---------------- K3: HMMA compensated GEMM, all-fp16 cp.async feed ----------------
#define STAGE_BYTES 49152
__global__ void __launch_bounds__(256, 2) hgemm(
    const __half* __restrict__ Ahi, const __half* __restrict__ Alo,
    const __half* __restrict__ Xhi, const __half* __restrict__ Xlo,
    float* __restrict__ C) {
    extern __shared__ __align__(1024) unsigned char sb[];
    const uint32_t s0 = smem_u32(sb);

    const int tid = threadIdx.x;
    const int wid = tid >> 5, lane = tid & 31;
    const int l0 = blockIdx.x * 64;
    const int m0 = blockIdx.y * 128;
    const int b  = blockIdx.z;

    const int m_base = (wid >> 1) * 32;
    const int n_base = (wid & 1) * 32;

    const __half* Xhi_b = Xhi + (size_t)b * CIN * LTOT;
    const __half* Xlo_b = Xlo + (size_t)b * CIN * LTOT;

    float acc[2][4][4];
#pragma unroll
    for (int mt = 0; mt < 2; mt++)
#pragma unroll
        for (int nt = 0; nt < 4; nt++)
#pragma unroll
            for (int i = 0; i < 4; i++) acc[mt][nt][i] = 0.f;

    auto load_chunk = [&](int c) {
        const int st = c & 1;
        const int k0 = c * 64;
        uint32_t dAhi = s0 + st * STAGE_BYTES;
        uint32_t dAlo = dAhi + 16384;
        uint32_t dXhi = dAhi + 32768;
        uint32_t dXlo = dAhi + 40960;
#pragma unroll
        for (int j = 0; j < 4; j++) {
            int idx = tid + j * 256;
            int row = idx >> 3, ch = idx & 7;
            uint32_t off = sw128(row * 128 + ch * 16);
            size_t gidx = (size_t)(m0 + row) * CIN + k0 + ch * 8;
            cp16(dAhi + off, Ahi + gidx);
            cp16(dAlo + off, Alo + gidx);
        }
#pragma unroll
        for (int j = 0; j < 2; j++) {
            int idx = tid + j * 256;
            int row = idx >> 3, ch = idx & 7;
            uint32_t off = sw128(row * 128 + ch * 16);
            size_t gidx = (size_t)(k0 + row) * LTOT + l0 + ch * 8;
            cp16(dXhi + off, Xhi_b + gidx);
            cp16(dXlo + off, Xlo_b + gidx);
        }
        CP_COMMIT();
    };

    load_chunk(0);
    const int b3 = lane >> 3, r8 = lane & 7;

    for (int c = 0; c < 4; c++) {
        if (c + 1 < 4) {
            load_chunk(c + 1);
            asm volatile("cp.async.wait_group 1;" ::: "memory");
        } else {
            asm volatile("cp.async.wait_group 0;" ::: "memory");
        }
        __syncthreads();

        const int st = c & 1;
        const uint32_t sAhi = s0 + st * STAGE_BYTES;
        const uint32_t sAlo = sAhi + 16384;
        const uint32_t sXhi = sAhi + 32768;
        const uint32_t sXlo = sAhi + 40960;

#pragma unroll
        for (int kk = 0; kk < 4; kk++) {
            uint32_t ahi[2][4], alo[2][4], bhi[2][4], blo[2][4];
#pragma unroll
            for (int mt = 0; mt < 2; mt++) {
                int row = m_base + mt * 16 + ((b3 & 1) << 3) + r8;
                uint32_t byte = sw128((uint32_t)(row * 128 + kk * 32 + ((b3 >> 1) << 4)));
                ldmA4(ahi[mt], sAhi + byte);
                ldmA4(alo[mt], sAlo + byte);
            }
#pragma unroll
            for (int g = 0; g < 2; g++) {
                int krow = kk * 16 + (lane & 15);
                int ncol = n_base + g * 16 + ((lane >> 4) << 3);
                uint32_t byte = sw128((uint32_t)(krow * 128 + ncol * 2));
                ldmBt4(bhi[g], sXhi + byte);
                ldmBt4(blo[g], sXlo + byte);
            }
#pragma unroll
            for (int mt = 0; mt < 2; mt++)
#pragma unroll
                for (int g = 0; g < 2; g++)
#pragma unroll
                    for (int h = 0; h < 2; h++) {
                        float* a = acc[mt][g * 2 + h];
                        hmma(a, ahi[mt], &bhi[g][h * 2]);   // hh
                        hmma(a, ahi[mt], &blo[g][h * 2]);   // hl
                        hmma(a, alo[mt], &bhi[g][h * 2]);   // lh
                    }
        }
        __syncthreads();
    }

    const int g = lane >> 2, j2 = (lane & 3) * 2;
    float* Cb = C + (size_t)b * DMODEL * LTOT;
#pragma unroll
    for (int mt = 0; mt < 2; mt++) {
        int mrow = m0 + m_base + mt * 16 + g;
#pragma unroll
        for (int nt = 0; nt < 4; nt++) {
            int col = l0 + n_base + nt * 8 + j2;
            *reinterpret_cast<float2*>(Cb + (size_t)mrow * LTOT + col) =
                make_float2(acc[mt][nt][0], acc[mt][nt][1]);
            *reinterpret_cast<float2*>(Cb + (size_t)(mrow + 8) * LTOT + col) =
                make_float2(acc[mt][nt][2], acc[mt][nt][3]);
        }
    }
}

// ---------------- K4: fused softmax + AV gather, fp16 hi/lo output ----------------
// grid (49, 128): one (b,h) and a 64-l tile per block; 256 threads.
__global__ void __launch_bounds__(256) attn_av_kernel(
    const float* __restrict__ pos_emb, const float* __restrict__ Wlin) {
    __shared__ float sm_at[KWIN][64];
    const int bh = blockIdx.y;
    const int b = bh >> 3, h = bh & 7;
    const int l0 = blockIdx.x * 64;
    const int tid = threadIdx.x;

    // phase 1: softmax for 64 positions
    if (tid < 64) {
        float scale = Wlin[0] + Wlin[1] + Wlin[2] + Wlin[3];
        int l = l0 + tid;
        int y = l / HDIM, xx = l % HDIM;
        const float* sp = g_s + (size_t)bh * LTOT;
        float logit[KWIN];
#pragma unroll
        for (int kh = 0; kh < 3; kh++)
#pragma unroll
            for (int kw = 0; kw < 3; kw++) {
                int yy = y + kh - 1, xz = xx + kw - 1;
                float sv = (yy >= 0 && yy < HDIM && xz >= 0 && xz < HDIM)
                               ? sp[yy * HDIM + xz] : 0.f;
                logit[kh * 3 + kw] = sv + pos_emb[kh + kw];
            }
        float m = logit[0];
#pragma unroll
        for (int k = 1; k < KWIN; k++) m = fmaxf(m, logit[k]);
        float e[KWIN], sum = 0.f;
#pragma unroll
        for (int k = 0; k < KWIN; k++) { e[k] = __expf(logit[k] - m); sum += e[k]; }
        float inv = scale / sum;
#pragma unroll
        for (int k = 0; k < KWIN; k++) sm_at[k][tid] = e[k] * inv;
    }
    __syncthreads();

    // phase 2: gather. warp = 4 channels; thread = 2 l x 4 channels.
    const int lp = tid & 31;                    // l-pair
    const int dg = tid >> 5;                    // 0..7 -> channels dg*4..dg*4+3
    float att[2][KWIN];
    int off[2][KWIN];
#pragma unroll
    for (int e = 0; e < 2; e++) {
        int ll = lp * 2 + e;
        int l = l0 + ll;
        int y = l / HDIM, xx = l % HDIM;
#pragma unroll
        for (int kh = 0; kh < 3; kh++)
#pragma unroll
            for (int kw = 0; kw < 3; kw++) {
                int k = kh * 3 + kw;
                int yy = y + kh - 1, xz = xx + kw - 1;
                bool ok = (yy >= 0 && yy < HDIM && xz >= 0 && xz < HDIM);
                att[e][k] = ok ? sm_at[k][ll] : 0.f;
                off[e][k] = ok ? yy * HDIM + xz : 0;
            }
    }
    const size_t base = (size_t)(b * DMODEL + h * NPH + dg * 4) * LTOT;
#pragma unroll
    for (int dd = 0; dd < 4; dd++) {
        const float* vp = g_v + base + (size_t)dd * LTOT;
        float o[2];
#pragma unroll
        for (int e = 0; e < 2; e++) {
            float a = 0.f;
#pragma unroll
            for (int k = 0; k < KWIN; k++) a += att[e][k] * vp[off[e][k]];
            o[e] = a;
        }
        __half2 h2 = __float22half2_rn(make_float2(o[0], o[1]));
        float2 hr = __half22float2(h2);
        __half2 l2 = __float22half2_rn(make_float2(o[0] - hr.x, o[1] - hr.y));
        size_t oidx = base + (size_t)dd * LTOT + l0 + lp * 2;
        *reinterpret_cast<__half2*>(g_ohi + oidx) = h2;
        *reinterpret_cast<__half2*>(g_olo + oidx) = l2;
    }
}

// ---------------- host launcher ----------------
extern "C" void kernel_launch(void* const* d_in, const int* in_sizes, int n_in,
                              void* d_out, int out_size) {
    const float* x       = (const float*)d_in[0];
    const float* q       = (const float*)d_in[1];
    const float* Wk      = (const float*)d_in[2];
    const float* Wv      = (const float*)d_in[3];
    const float* pos_emb = (const float*)d_in[4];
    const float* Wlin    = (const float*)d_in[5];
    const float* Wproj   = (const float*)d_in[6];
    float* out = (float*)d_out;

    void *pv, *pxhi, *pxlo, *pohi, *polo, *pwvhi, *pwvlo, *pwphi, *pwplo;
    cudaGetSymbolAddress(&pv, g_v);
    cudaGetSymbolAddress(&pxhi, g_xhi);
    cudaGetSymbolAddress(&pxlo, g_xlo);
    cudaGetSymbolAddress(&pohi, g_ohi);
    cudaGetSymbolAddress(&polo, g_olo);
    cudaGetSymbolAddress(&pwvhi, g_wvhi);
    cudaGetSymbolAddress(&pwvlo, g_wvlo);
    cudaGetSymbolAddress(&pwphi, g_wphi);
    cudaGetSymbolAddress(&pwplo, g_wplo);

    static bool attr_set = false;
    if (!attr_set) {
        cudaFuncSetAttribute(hgemm, cudaFuncAttributeMaxDynamicSharedMemorySize,
                             2 * STAGE_BYTES);
        attr_set = true;
    }

    const int WN4 = DMODEL * CIN / 4;
    const int SMEM = 2 * STAGE_BYTES;

    wq_kernel<<<BATCH * HEADS, 256>>>(q, Wk);
    split_kernel<<<(WN4 + 255) / 256, 256>>>(Wv, (__half*)pwvhi, (__half*)pwvlo, WN4);
    split_kernel<<<(WN4 + 255) / 256, 256>>>(Wproj, (__half*)pwphi, (__half*)pwplo, WN4);
    s_split_kernel<<<dim3(LTOT / 64, BATCH), 256>>>(x);

    hgemm<<<dim3(LTOT / 64, DMODEL / 128, BATCH), 256, SMEM>>>(
        (const __half*)pwvhi, (const __half*)pwvlo,
        (const __half*)pxhi, (const __half*)pxlo, (float*)pv);

    attn_av_kernel<<<dim3(LTOT / 64, BATCH * HEADS), 256>>>(pos_emb, Wlin);

    hgemm<<<dim3(LTOT / 64, DMODEL / 128, BATCH), 256, SMEM>>>(
        (const __half*)pwphi, (const __half*)pwplo,
        (const __half*)pohi, (const __half*)polo, out);
}